// round 8
// baseline (speedup 1.0000x reference)
#include <cuda_runtime.h>
#include <math.h>
#include <stdint.h>

#define HEADS 4
#define BB 8
#define NN 1024
#define CC 256
#define DD 64
#define QT 128
#define NC 128
#define NCHUNK 8
#define THREADS 512

#define QP 68           // pitches (floats); %32 = 4 / 4 / 8 / 4 -> conflict-free frags
#define KP 68
#define VP 72
#define PP 132

#define SQ_F  0
#define SK0_F (SQ_F + QT*QP)          // 8704
#define SK1_F (SK0_F + NC*KP)         // 17408
#define SV_F  (SK1_F + NC*KP)         // 26112
#define SP_F  (SV_F + NC*VP)          // 35328
#define RS_F  (SP_F + QT*PP)          // 52224
#define SMEM_FLOATS (RS_F + 128)
#define SMEM_BYTES  (SMEM_FLOATS * 4) // 209408

#define NEGINF __int_as_float(0xff800000)

#define CP_COMMIT  asm volatile("cp.async.commit_group;" ::: "memory")
#define CP_WAIT(N) asm volatile("cp.async.wait_group " #N ";" ::: "memory")

static __device__ __forceinline__ uint32_t s2u(const void* p){
    uint32_t a;
    asm("{ .reg .u64 t; cvta.to.shared.u64 t, %1; cvt.u32.u64 %0, t; }" : "=r"(a) : "l"(p));
    return a;
}
static __device__ __forceinline__ uint32_t f2tf32(float f){
    uint32_t u; asm("cvt.rna.tf32.f32 %0, %1;" : "=r"(u) : "f"(f)); return u;
}
static __device__ __forceinline__ void mma_tf32(float* c, const uint32_t* a,
                                                uint32_t b0, uint32_t b1){
    asm volatile("mma.sync.aligned.m16n8k8.row.col.f32.tf32.tf32.f32 "
        "{%0,%1,%2,%3}, {%4,%5,%6,%7}, {%8,%9}, {%0,%1,%2,%3};"
        : "+f"(c[0]), "+f"(c[1]), "+f"(c[2]), "+f"(c[3])
        : "r"(a[0]), "r"(a[1]), "r"(a[2]), "r"(a[3]), "r"(b0), "r"(b1));
}
// async-copy a 128-row x 64-float tile (gmem pitch CC) into smem with given pitch
static __device__ __forceinline__ void cp_tile(uint32_t sm_byte_base, const float* g,
                                               int tid, int pitch){
    int r0 = tid >> 4;             // 0..31
    int seg = (tid & 15) * 4;      // 0..60 floats
    #pragma unroll
    for (int i = 0; i < 4; i++){
        int row = r0 + 32*i;
        uint32_t dst = sm_byte_base + (uint32_t)(row * pitch + seg) * 4u;
        const float* src = g + (size_t)row * CC + seg;
        asm volatile("cp.async.ca.shared.global [%0], [%1], 16;" :: "r"(dst), "l"(src));
    }
}

__global__ __launch_bounds__(THREADS, 1)
void attn_hmma2_kernel(const float* __restrict__ q,
                       const float* __restrict__ k,
                       const float* __restrict__ v,
                       const unsigned int* __restrict__ mask,
                       const float* __restrict__ dis,
                       float* __restrict__ out,
                       float* __restrict__ pout)
{
    extern __shared__ float smf[];
    uint32_t* smu = (uint32_t*)smf;
    const uint32_t sbase = s2u(smf);

    const int tid  = threadIdx.x;
    const int wid  = tid >> 5;
    const int lane = tid & 31;
    const int wr   = wid >> 2;          // row group 0..3 (32 rows)
    const int wc   = wid & 3;           // col group 0..3
    const int h    = blockIdx.x & 3;    // heads fastest -> dis/mask L2 reuse
    const int tile = blockIdx.x >> 2;
    const int b    = blockIdx.y;
    const int row0 = tile * QT;

    const float* qbase = q + ((size_t)b * NN + row0) * CC + h * DD;
    const float* kbase = k + ((size_t)b * NN) * CC + h * DD;
    const float* vbase = v + ((size_t)b * NN) * CC + h * DD;
    const float* disbase = dis + ((size_t)b * NN + row0) * NN;
    const unsigned int* mbase = mask + ((size_t)b * NN + row0) * NN;
    float* pbase = pout + (((size_t)h * BB + b) * NN + row0) * NN;

    // prologue: async-stage K[0] into buf0
    cp_tile(sbase + SK0_F*4u, kbase, tid, KP);
    CP_COMMIT;

    // stage Q once (fp32 -> tf32 rna), pitch QP
    {
        int r = tid >> 2, seg = (tid & 3) * 16;
        const float* src = qbase + (size_t)r * CC + seg;
        uint32_t* d = smu + SQ_F + r * QP + seg;
        #pragma unroll
        for (int i = 0; i < 4; i++){
            float4 vv = *(const float4*)(src + 4*i);
            uint4 o; o.x=f2tf32(vv.x); o.y=f2tf32(vv.y); o.z=f2tf32(vv.z); o.w=f2tf32(vv.w);
            *(uint4*)(d + 4*i) = o;
        }
    }
    if (tid < 128) smf[RS_F + tid] = 0.0f;

    const int fr = lane >> 2;      // fragment row within 8
    const int fq = lane & 3;       // fragment quad col
    float psum[2][2] = {{0.f,0.f},{0.f,0.f}};

    // ====================== PASS 1: rowsums ======================
    for (int kc = 0; kc < NCHUNK; kc++){
        CP_WAIT(0);                    // K[kc] landed
        __syncthreads();               // also closes prev chunk's K-buffer reads
        cp_tile(sbase + (uint32_t)(((kc+1)&1) ? SK1_F : SK0_F)*4u,
                kbase + (size_t)(((kc+1)&7) * NC) * CC, tid, KP);
        CP_COMMIT;

        const float* sK = smf + ((kc & 1) ? SK1_F : SK0_F);

        float sacc[2][4][4];
        #pragma unroll
        for (int rt = 0; rt < 2; rt++)
            #pragma unroll
            for (int ct = 0; ct < 4; ct++)
                #pragma unroll
                for (int i = 0; i < 4; i++) sacc[rt][ct][i] = 0.0f;

        #pragma unroll
        for (int kt = 0; kt < 8; kt++){
            const int k0 = 8*kt + fq;
            uint32_t a[2][4];
            #pragma unroll
            for (int rt = 0; rt < 2; rt++){
                const uint32_t* q0 = smu + SQ_F + (wr*32 + 16*rt + fr) * QP + k0;
                a[rt][0] = q0[0];
                a[rt][1] = q0[8*QP];
                a[rt][2] = q0[4];
                a[rt][3] = q0[8*QP + 4];
            }
            #pragma unroll
            for (int ct = 0; ct < 4; ct++){
                const float* kp = sK + (wc*32 + 8*ct + fr) * KP + k0;
                uint32_t b0 = f2tf32(kp[0]), b1 = f2tf32(kp[4]);
                mma_tf32(sacc[0][ct], a[0], b0, b1);
                mma_tf32(sacc[1][ct], a[1], b0, b1);
            }
        }

        #pragma unroll
        for (int rt = 0; rt < 2; rt++){
            int row = wr*32 + 16*rt + fr;
            const float* dp0 = disbase + (size_t)row * NN + kc*NC;
            const unsigned int* mp0 = mbase + (size_t)row * NN + kc*NC;
            #pragma unroll
            for (int ct = 0; ct < 4; ct++){
                int col = wc*32 + 8*ct + 2*fq;
                float2 d0 = *(const float2*)(dp0 + col);
                float2 d1 = *(const float2*)(dp0 + 8*NN + col);
                uint2  m0 = *(const uint2*) (mp0 + col);
                uint2  m1 = *(const uint2*) (mp0 + 8*NN + col);
                if (m0.x) d0.x = NEGINF;
                if (m0.y) d0.y = NEGINF;
                if (m1.x) d1.x = NEGINF;
                if (m1.y) d1.y = NEGINF;
                psum[rt][0] += __expf((sacc[rt][ct][0] + d0.x) * 0.125f)
                             + __expf((sacc[rt][ct][1] + d0.y) * 0.125f);
                psum[rt][1] += __expf((sacc[rt][ct][2] + d1.x) * 0.125f)
                             + __expf((sacc[rt][ct][3] + d1.y) * 0.125f);
            }
        }
    }

    // rowsum reduce: quad shuffle then smem atomics (4 col-group warps per row)
    #pragma unroll
    for (int rt = 0; rt < 2; rt++)
        #pragma unroll
        for (int hf = 0; hf < 2; hf++){
            float vs = psum[rt][hf];
            vs += __shfl_xor_sync(0xffffffffu, vs, 1);
            vs += __shfl_xor_sync(0xffffffffu, vs, 2);
            if (fq == 0)
                atomicAdd(smf + RS_F + wr*32 + 16*rt + 8*hf + fr, vs);
        }
    __syncthreads();
    float inv[2][2];
    #pragma unroll
    for (int rt = 0; rt < 2; rt++)
        #pragma unroll
        for (int hf = 0; hf < 2; hf++)
            inv[rt][hf] = 1.0f / smf[RS_F + wr*32 + 16*rt + 8*hf + fr];

    // ====================== PASS 2: P + O ======================
    float oacc[2][2][4];
    #pragma unroll
    for (int rt = 0; rt < 2; rt++)
        #pragma unroll
        for (int dt = 0; dt < 2; dt++)
            #pragma unroll
            for (int i = 0; i < 4; i++) oacc[rt][dt][i] = 0.0f;

    for (int kc = 0; kc < NCHUNK; kc++){
        CP_WAIT(0);                    // K[kc] landed (incl. pass1's wrap prefetch at kc=0)
        __syncthreads();               // closes prev chunk's V/P-smem/K-buf reads
        cp_tile(sbase + SV_F*4u, vbase + (size_t)(kc*NC) * CC, tid, VP);
        CP_COMMIT;                     // group: V[kc]
        cp_tile(sbase + (uint32_t)(((kc+1)&1) ? SK1_F : SK0_F)*4u,
                kbase + (size_t)(((kc+1)&7) * NC) * CC, tid, KP);
        CP_COMMIT;                     // group: K[next]

        const float* sK = smf + ((kc & 1) ? SK1_F : SK0_F);

        float sacc[2][4][4];
        #pragma unroll
        for (int rt = 0; rt < 2; rt++)
            #pragma unroll
            for (int ct = 0; ct < 4; ct++)
                #pragma unroll
                for (int i = 0; i < 4; i++) sacc[rt][ct][i] = 0.0f;

        #pragma unroll
        for (int kt = 0; kt < 8; kt++){
            const int k0 = 8*kt + fq;
            uint32_t a[2][4];
            #pragma unroll
            for (int rt = 0; rt < 2; rt++){
                const uint32_t* q0 = smu + SQ_F + (wr*32 + 16*rt + fr) * QP + k0;
                a[rt][0] = q0[0];
                a[rt][1] = q0[8*QP];
                a[rt][2] = q0[4];
                a[rt][3] = q0[8*QP + 4];
            }
            #pragma unroll
            for (int ct = 0; ct < 4; ct++){
                const float* kp = sK + (wc*32 + 8*ct + fr) * KP + k0;
                uint32_t b0 = f2tf32(kp[0]), b1 = f2tf32(kp[4]);
                mma_tf32(sacc[0][ct], a[0], b0, b1);
                mma_tf32(sacc[1][ct], a[1], b0, b1);
            }
        }

        // exp -> normalized P (tf32 bits) into smem staging
        #pragma unroll
        for (int rt = 0; rt < 2; rt++){
            int row = wr*32 + 16*rt + fr;
            const float* dp0 = disbase + (size_t)row * NN + kc*NC;
            const unsigned int* mp0 = mbase + (size_t)row * NN + kc*NC;
            #pragma unroll
            for (int ct = 0; ct < 4; ct++){
                int col = wc*32 + 8*ct + 2*fq;
                float2 d0 = *(const float2*)(dp0 + col);
                float2 d1 = *(const float2*)(dp0 + 8*NN + col);
                uint2  m0 = *(const uint2*) (mp0 + col);
                uint2  m1 = *(const uint2*) (mp0 + 8*NN + col);
                if (m0.x) d0.x = NEGINF;
                if (m0.y) d0.y = NEGINF;
                if (m1.x) d1.x = NEGINF;
                if (m1.y) d1.y = NEGINF;
                uint32_t p0 = f2tf32(__expf((sacc[rt][ct][0] + d0.x) * 0.125f) * inv[rt][0]);
                uint32_t p1 = f2tf32(__expf((sacc[rt][ct][1] + d0.y) * 0.125f) * inv[rt][0]);
                uint32_t p2 = f2tf32(__expf((sacc[rt][ct][2] + d1.x) * 0.125f) * inv[rt][1]);
                uint32_t p3 = f2tf32(__expf((sacc[rt][ct][3] + d1.y) * 0.125f) * inv[rt][1]);
                *(uint2*)(smu + SP_F + row*PP + col)       = make_uint2(p0, p1);
                *(uint2*)(smu + SP_F + (row+8)*PP + col)   = make_uint2(p2, p3);
            }
        }
        CP_WAIT(1);                    // V[kc] landed (K[next] may still fly)
        __syncthreads();               // P staged by all warps

        // PV: O[32x16 warp tile] += P[32x128] * V[128x16]
        const float* sV = smf + SV_F;
        #pragma unroll
        for (int kt = 0; kt < 16; kt++){
            const int k0 = 8*kt + fq;
            uint32_t a[2][4];
            #pragma unroll
            for (int rt = 0; rt < 2; rt++){
                const uint32_t* pp = smu + SP_F + (wr*32 + 16*rt + fr) * PP + k0;
                a[rt][0] = pp[0];
                a[rt][1] = pp[8*PP];
                a[rt][2] = pp[4];
                a[rt][3] = pp[8*PP + 4];
            }
            #pragma unroll
            for (int dt = 0; dt < 2; dt++){
                int dcol = wc*16 + 8*dt + fr;
                uint32_t b0 = f2tf32(sV[(size_t)k0 * VP + dcol]);
                uint32_t b1 = f2tf32(sV[(size_t)(k0 + 4) * VP + dcol]);
                mma_tf32(oacc[0][dt], a[0], b0, b1);
                mma_tf32(oacc[1][dt], a[1], b0, b1);
            }
        }

        // coalesced p_attn store from smem
        {
            int pr = tid >> 2, pq = tid & 3;
            const float* src = smf + SP_F + pr*PP + pq*32;
            float* dst = pbase + (size_t)pr * NN + kc*NC + pq*32;
            #pragma unroll
            for (int i = 0; i < 8; i++)
                *(float4*)(dst + 4*i) = *(const float4*)(src + 4*i);
        }
    }

    // ---- write O ----
    #pragma unroll
    for (int rt = 0; rt < 2; rt++){
        int gr = row0 + wr*32 + 16*rt + fr;
        #pragma unroll
        for (int dt = 0; dt < 2; dt++){
            int gc = h * DD + wc*16 + 8*dt + 2*fq;
            float* o0 = out + ((size_t)b * NN + gr) * CC + gc;
            *(float2*)o0          = make_float2(oacc[rt][dt][0], oacc[rt][dt][1]);
            *(float2*)(o0 + 8*CC) = make_float2(oacc[rt][dt][2], oacc[rt][dt][3]);
        }
    }
}

extern "C" void kernel_launch(void* const* d_in, const int* in_sizes, int n_in,
                              void* d_out, int out_size) {
    const float* q = (const float*)d_in[0];
    const float* k = (const float*)d_in[1];
    const float* v = (const float*)d_in[2];
    const unsigned int* mask = (const unsigned int*)d_in[3];
    const float* dis = (const float*)d_in[4];

    float* out  = (float*)d_out;
    float* pout = out + (size_t)BB * NN * CC;

    cudaFuncSetAttribute(attn_hmma2_kernel,
                         cudaFuncAttributeMaxDynamicSharedMemorySize, SMEM_BYTES);

    dim3 grid(HEADS * (NN / QT), BB, 1);
    attn_hmma2_kernel<<<grid, THREADS, SMEM_BYTES>>>(q, k, v, mask, dis, out, pout);
}

// round 9
// speedup vs baseline: 1.8315x; 1.8315x over previous
#include <cuda_runtime.h>
#include <math.h>
#include <stdint.h>

#define HEADS 4
#define BB 8
#define NN 1024
#define CC 256
#define DD 64
#define QT 32            // query rows per CTA (full 1024-col S strip in smem)
#define KC 64            // keys per sub-chunk
#define NCH 16           // sub-chunks

#define SPP 1028         // S pitch (%32==4 -> conflict-free frag+float4 access)
#define QP 68
#define KP 68
#define VP 72            // %32==8 -> conflict-free B frags

#define S_F   0
#define Q_F   (QT*SPP)             // 32896
#define K_F   (Q_F + QT*QP)        // 35072 (2 bufs of KC*KP)
#define V_F   (K_F + 2*KC*KP)      // 43776 (2 bufs of KC*VP)
#define RS_F  (V_F + 2*KC*VP)      // 52992
#define SMEM_FLOATS (RS_F + QT)
#define SMEM_BYTES (SMEM_FLOATS * 4)   // 212096

#define CP_COMMIT   asm volatile("cp.async.commit_group;" ::: "memory")
#define CP_WAIT0    asm volatile("cp.async.wait_group 0;" ::: "memory")
#define CP_WAIT1    asm volatile("cp.async.wait_group 1;" ::: "memory")

static __device__ __forceinline__ uint32_t s2u(const void* p){
    uint32_t a;
    asm("{ .reg .u64 t; cvta.to.shared.u64 t, %1; cvt.u32.u64 %0, t; }" : "=r"(a) : "l"(p));
    return a;
}
static __device__ __forceinline__ uint32_t f2tf32(float f){
    uint32_t u; asm("cvt.rna.tf32.f32 %0, %1;" : "=r"(u) : "f"(f)); return u;
}
static __device__ __forceinline__ void mma_tf32(float* c, const uint32_t* a,
                                                uint32_t b0, uint32_t b1){
    asm volatile("mma.sync.aligned.m16n8k8.row.col.f32.tf32.tf32.f32 "
        "{%0,%1,%2,%3}, {%4,%5,%6,%7}, {%8,%9}, {%0,%1,%2,%3};"
        : "+f"(c[0]), "+f"(c[1]), "+f"(c[2]), "+f"(c[3])
        : "r"(a[0]), "r"(a[1]), "r"(a[2]), "r"(a[3]), "r"(b0), "r"(b1));
}
// async-copy a KC x 64-float tile (gmem pitch CC) into smem at given pitch
static __device__ __forceinline__ void cp_tile64(uint32_t dst_bytes, const float* g,
                                                 int tid, int pitch){
    int r  = tid >> 2;           // 0..63
    int c0 = (tid & 3) * 16;     // float offset within row
    uint32_t dst = dst_bytes + (uint32_t)(r * pitch + c0) * 4u;
    const float* src = g + (size_t)r * CC + c0;
    #pragma unroll
    for (int i = 0; i < 4; i++)
        asm volatile("cp.async.ca.shared.global [%0], [%1], 16;"
                     :: "r"(dst + 16u*i), "l"(src + 4*i) : "memory");
}

__global__ __launch_bounds__(256, 1)
void attn_sp_kernel(const float* __restrict__ q,
                    const float* __restrict__ k,
                    const float* __restrict__ v,
                    const unsigned int* __restrict__ mask,
                    const float* __restrict__ dis,
                    float* __restrict__ out,
                    float* __restrict__ pout)
{
    extern __shared__ float smf[];
    uint32_t* smu = (uint32_t*)smf;
    const uint32_t sbase = s2u(smf);

    const int tid  = threadIdx.x;
    const int wid  = tid >> 5;
    const int lane = tid & 31;
    const int fr = lane >> 2, fq = lane & 3;
    const int wr = wid >> 2, wc = wid & 3;     // 2 row-groups x 4 col-groups
    const int h    = blockIdx.x & 3;           // heads fastest -> dis/mask L2 reuse
    const int tile = blockIdx.x >> 2;
    const int b    = blockIdx.y;
    const int row0 = tile * QT;

    const float* qbase = q + ((size_t)b * NN + row0) * CC + h * DD;
    const float* kbase = k + ((size_t)b * NN) * CC + h * DD;
    const float* vbase = v + ((size_t)b * NN) * CC + h * DD;
    const float* disbase = dis + ((size_t)b * NN + row0) * NN;
    const unsigned int* mbase = mask + ((size_t)b * NN + row0) * NN;
    float* pbase = pout + (((size_t)h * BB + b) * NN + row0) * NN;

    // prologue: async-stage K[0], K[1]
    cp_tile64(sbase + K_F*4u, kbase, tid, KP);              CP_COMMIT;
    cp_tile64(sbase + (K_F + KC*KP)*4u, kbase + (size_t)KC*CC, tid, KP); CP_COMMIT;

    // stage Q once (fp32 -> tf32 rna)
    {
        int r = tid >> 3, seg = (tid & 7) * 8;
        const float* src = qbase + (size_t)r * CC + seg;
        float4 v0 = *(const float4*)src;
        float4 v1 = *(const float4*)(src + 4);
        uint32_t* d = smu + Q_F + r * QP + seg;
        *(uint4*)d       = make_uint4(f2tf32(v0.x), f2tf32(v0.y), f2tf32(v0.z), f2tf32(v0.w));
        *(uint4*)(d + 4) = make_uint4(f2tf32(v1.x), f2tf32(v1.y), f2tf32(v1.z), f2tf32(v1.w));
    }

    const int erow = tid >> 3, eoct = tid & 7;  // exp-pass coords (row, col-octet)
    float psum = 0.0f;

    // ================= SINGLE S PASS: MMA + exp -> unnormalized P in smem =================
    for (int c = 0; c < NCH; c++){
        CP_WAIT1;                      // K[c] landed (K[c+1] or V[0] may fly)
        __syncthreads();

        // prefetch dis/mask for this chunk into registers (overlaps the MMAs)
        float4 dv0, dv1; uint4 mv0, mv1;
        {
            const float* dp = disbase + (size_t)erow * NN + c*KC + eoct*4;
            const unsigned int* mp = mbase + (size_t)erow * NN + c*KC + eoct*4;
            dv0 = *(const float4*)dp;        dv1 = *(const float4*)(dp + 32);
            mv0 = *(const uint4*)mp;         mv1 = *(const uint4*)(mp + 32);
        }

        const float* sK = smf + K_F + (c & 1) * KC * KP;
        float sacc[2][4] = {{0.f,0.f,0.f,0.f},{0.f,0.f,0.f,0.f}};
        #pragma unroll
        for (int kt = 0; kt < 8; kt++){
            const int k0 = 8*kt + fq;
            const uint32_t* q0 = smu + Q_F + (wr*16 + fr) * QP + k0;
            uint32_t a[4] = { q0[0], q0[8*QP], q0[4], q0[8*QP + 4] };
            #pragma unroll
            for (int ct = 0; ct < 2; ct++){
                const float* kp = sK + (wc*16 + 8*ct + fr) * KP + k0;
                uint32_t b0 = f2tf32(kp[0]), b1 = f2tf32(kp[4]);
                mma_tf32(sacc[ct], a, b0, b1);
            }
        }
        // store raw S frags
        #pragma unroll
        for (int ct = 0; ct < 2; ct++){
            int col = c*KC + wc*16 + 8*ct + 2*fq;
            int row = wr*16 + fr;
            *(float2*)(smf + S_F + row*SPP + col)     = make_float2(sacc[ct][0], sacc[ct][1]);
            *(float2*)(smf + S_F + (row+8)*SPP + col) = make_float2(sacc[ct][2], sacc[ct][3]);
        }
        __syncthreads();               // frags visible; K buffer reads done

        // prefetch next K (or first V tiles at the tail)
        if (c < NCH-2){
            cp_tile64(sbase + (K_F + (c & 1)*KC*KP)*4u,
                      kbase + (size_t)(c+2)*KC*CC, tid, KP); CP_COMMIT;
        } else if (c == NCH-2){
            cp_tile64(sbase + V_F*4u, vbase, tid, VP); CP_COMMIT;
        } else {
            cp_tile64(sbase + (V_F + KC*VP)*4u, vbase + (size_t)KC*CC, tid, VP); CP_COMMIT;
        }

        // exp pass (coalesced): P = mask ? 0 : exp((S+dis)/8), unnormalized
        {
            float* sp = smf + S_F + erow*SPP + c*KC + eoct*4;
            float4 sv0 = *(const float4*)sp;
            float4 sv1 = *(const float4*)(sp + 32);
            float e0 = mv0.x ? 0.f : __expf((sv0.x + dv0.x) * 0.125f);
            float e1 = mv0.y ? 0.f : __expf((sv0.y + dv0.y) * 0.125f);
            float e2 = mv0.z ? 0.f : __expf((sv0.z + dv0.z) * 0.125f);
            float e3 = mv0.w ? 0.f : __expf((sv0.w + dv0.w) * 0.125f);
            float e4 = mv1.x ? 0.f : __expf((sv1.x + dv1.x) * 0.125f);
            float e5 = mv1.y ? 0.f : __expf((sv1.y + dv1.y) * 0.125f);
            float e6 = mv1.z ? 0.f : __expf((sv1.z + dv1.z) * 0.125f);
            float e7 = mv1.w ? 0.f : __expf((sv1.w + dv1.w) * 0.125f);
            psum += (e0+e1) + (e2+e3) + (e4+e5) + (e6+e7);
            *(float4*)sp        = make_float4(e0,e1,e2,e3);
            *(float4*)(sp + 32) = make_float4(e4,e5,e6,e7);
        }
    }

    // ---- rowsum reduce (8 lanes per row, unique writer) ----
    {
        float vs = psum;
        vs += __shfl_xor_sync(0xffffffffu, vs, 1);
        vs += __shfl_xor_sync(0xffffffffu, vs, 2);
        vs += __shfl_xor_sync(0xffffffffu, vs, 4);
        if (eoct == 0) smf[RS_F + erow] = vs;
    }
    __syncthreads();
    const float myinv = 1.0f / smf[RS_F + erow];
    const float invA  = 1.0f / smf[RS_F + wr*16 + fr];
    const float invB  = 1.0f / smf[RS_F + wr*16 + fr + 8];

    // ================= PV + normalized P store =================
    float oacc[2][4] = {{0.f,0.f,0.f,0.f},{0.f,0.f,0.f,0.f}};
    for (int p = 0; p < NCH; p++){
        if (p == NCH-1) { CP_WAIT0; } else { CP_WAIT1; }   // V[p] landed
        __syncthreads();
        const float* sV = smf + V_F + (p & 1) * KC * VP;

        #pragma unroll
        for (int kt = 0; kt < 8; kt++){
            const int k0 = p*KC + 8*kt + fq;
            const float* pp = smf + S_F + (wr*16 + fr) * SPP + k0;
            uint32_t a[4] = { f2tf32(pp[0]), f2tf32(pp[8*SPP]),
                              f2tf32(pp[4]), f2tf32(pp[8*SPP + 4]) };
            #pragma unroll
            for (int dt = 0; dt < 2; dt++){
                const int dcol = wc*16 + 8*dt + fr;
                uint32_t b0 = f2tf32(sV[(size_t)(8*kt + fq) * VP + dcol]);
                uint32_t b1 = f2tf32(sV[(size_t)(8*kt + fq + 4) * VP + dcol]);
                mma_tf32(oacc[dt], a, b0, b1);
            }
        }

        // normalized p_attn store (coalesced float4)
        {
            const float* sp = smf + S_F + erow*SPP + p*KC + eoct*4;
            float* dst = pbase + (size_t)erow * NN + p*KC + eoct*4;
            float4 p0 = *(const float4*)sp;
            float4 p1 = *(const float4*)(sp + 32);
            *(float4*)dst        = make_float4(p0.x*myinv, p0.y*myinv, p0.z*myinv, p0.w*myinv);
            *(float4*)(dst + 32) = make_float4(p1.x*myinv, p1.y*myinv, p1.z*myinv, p1.w*myinv);
        }
        __syncthreads();               // V buffer reads done before overwrite
        if (p < NCH-2){
            cp_tile64(sbase + (V_F + (p & 1)*KC*VP)*4u,
                      vbase + (size_t)(p+2)*KC*CC, tid, VP); CP_COMMIT;
        }
    }

    // ---- write O (scaled by row inv) ----
    #pragma unroll
    for (int dt = 0; dt < 2; dt++){
        int gc = h*DD + wc*16 + 8*dt + 2*fq;
        float* o0 = out + ((size_t)b * NN + row0 + wr*16 + fr) * CC + gc;
        *(float2*)o0          = make_float2(oacc[dt][0]*invA, oacc[dt][1]*invA);
        *(float2*)(o0 + 8*CC) = make_float2(oacc[dt][2]*invB, oacc[dt][3]*invB);
    }
}

extern "C" void kernel_launch(void* const* d_in, const int* in_sizes, int n_in,
                              void* d_out, int out_size) {
    const float* q = (const float*)d_in[0];
    const float* k = (const float*)d_in[1];
    const float* v = (const float*)d_in[2];
    const unsigned int* mask = (const unsigned int*)d_in[3];
    const float* dis = (const float*)d_in[4];

    float* out  = (float*)d_out;
    float* pout = out + (size_t)BB * NN * CC;

    cudaFuncSetAttribute(attn_sp_kernel,
                         cudaFuncAttributeMaxDynamicSharedMemorySize, SMEM_BYTES);

    dim3 grid((NN / QT) * HEADS, BB, 1);
    attn_sp_kernel<<<grid, 256, SMEM_BYTES>>>(q, k, v, mask, dis, out, pout);
}

// round 11
// speedup vs baseline: 1.8804x; 1.0267x over previous
#include <cuda_runtime.h>
#include <math.h>
#include <stdint.h>

#define HEADS 4
#define BB 8
#define NN 1024
#define CC 256
#define DD 64
#define QT 32            // query rows per CTA (full 1024-col S strip in smem)
#define KC 64            // keys per sub-chunk
#define NCH 16           // sub-chunks

#define SPP 1028         // S pitch (%32==4 -> conflict-free frag+float4 access)
#define QP 68
#define KP 68
#define VP 72            // %32==8 -> conflict-free B frags

#define S_F   0
#define Q_F   (QT*SPP)             // 32896
#define K_F   (Q_F + QT*QP)        // 35072 (2 bufs of KC*KP)
#define V_F   (K_F + 2*KC*KP)      // 43776 (2 bufs of KC*VP)
#define RS_F  (V_F + 2*KC*VP)      // 52992
#define SMEM_FLOATS (RS_F + QT)
#define SMEM_BYTES (SMEM_FLOATS * 4)   // 212096

#define CP_COMMIT   asm volatile("cp.async.commit_group;" ::: "memory")
#define CP_WAIT0    asm volatile("cp.async.wait_group 0;" ::: "memory")
#define CP_WAIT1    asm volatile("cp.async.wait_group 1;" ::: "memory")

static __device__ __forceinline__ uint32_t s2u(const void* p){
    uint32_t a;
    asm("{ .reg .u64 t; cvta.to.shared.u64 t, %1; cvt.u32.u64 %0, t; }" : "=r"(a) : "l"(p));
    return a;
}
static __device__ __forceinline__ uint32_t f2tf32(float f){
    uint32_t u; asm("cvt.rna.tf32.f32 %0, %1;" : "=r"(u) : "f"(f)); return u;
}
static __device__ __forceinline__ void mma_tf32(float* c, const uint32_t* a,
                                                uint32_t b0, uint32_t b1){
    asm volatile("mma.sync.aligned.m16n8k8.row.col.f32.tf32.tf32.f32 "
        "{%0,%1,%2,%3}, {%4,%5,%6,%7}, {%8,%9}, {%0,%1,%2,%3};"
        : "+f"(c[0]), "+f"(c[1]), "+f"(c[2]), "+f"(c[3])
        : "r"(a[0]), "r"(a[1]), "r"(a[2]), "r"(a[3]), "r"(b0), "r"(b1));
}
// async-copy a KC x 64-float tile (gmem pitch CC) into smem at given pitch
static __device__ __forceinline__ void cp_tile64(uint32_t dst_bytes, const float* g,
                                                 int tid, int pitch){
    int r  = tid >> 2;           // 0..63
    int c0 = (tid & 3) * 16;     // float offset within row
    uint32_t dst = dst_bytes + (uint32_t)(r * pitch + c0) * 4u;
    const float* src = g + (size_t)r * CC + c0;
    #pragma unroll
    for (int i = 0; i < 4; i++)
        asm volatile("cp.async.ca.shared.global [%0], [%1], 16;"
                     :: "r"(dst + 16u*i), "l"(src + 4*i) : "memory");
}

__global__ __launch_bounds__(256, 1)
void attn_sp2_kernel(const float* __restrict__ q,
                     const float* __restrict__ k,
                     const float* __restrict__ v,
                     const unsigned int* __restrict__ mask,
                     const float* __restrict__ dis,
                     float* __restrict__ out,
                     float* __restrict__ pout)
{
    extern __shared__ float smf[];
    uint32_t* smu = (uint32_t*)smf;
    const uint32_t sbase = s2u(smf);

    const int tid  = threadIdx.x;
    const int wid  = tid >> 5;
    const int lane = tid & 31;
    const int fr = lane >> 2, fq = lane & 3;
    const int wr = wid >> 2, wc = wid & 3;     // 2 row-groups x 4 col-groups
    const int h    = blockIdx.x & 3;           // heads fastest -> dis/mask L2 reuse
    const int tile = blockIdx.x >> 2;
    const int b    = blockIdx.y;
    const int row0 = tile * QT;

    const float* qbase = q + ((size_t)b * NN + row0) * CC + h * DD;
    const float* kbase = k + ((size_t)b * NN) * CC + h * DD;
    const float* vbase = v + ((size_t)b * NN) * CC + h * DD;
    const float* disbase = dis + ((size_t)b * NN + row0) * NN;
    const unsigned int* mbase = mask + ((size_t)b * NN + row0) * NN;
    float* pbase = pout + (((size_t)h * BB + b) * NN + row0) * NN;

    // prologue: async-stage K[0], K[1]
    cp_tile64(sbase + K_F*4u, kbase, tid, KP);              CP_COMMIT;
    cp_tile64(sbase + (K_F + KC*KP)*4u, kbase + (size_t)KC*CC, tid, KP); CP_COMMIT;

    // stage Q once (fp32 -> tf32 rna)
    {
        int r = tid >> 3, seg = (tid & 7) * 8;
        const float* src = qbase + (size_t)r * CC + seg;
        float4 v0 = *(const float4*)src;
        float4 v1 = *(const float4*)(src + 4);
        uint32_t* d = smu + Q_F + r * QP + seg;
        *(uint4*)d       = make_uint4(f2tf32(v0.x), f2tf32(v0.y), f2tf32(v0.z), f2tf32(v0.w));
        *(uint4*)(d + 4) = make_uint4(f2tf32(v1.x), f2tf32(v1.y), f2tf32(v1.z), f2tf32(v1.w));
    }
    __syncthreads();

    // ---- hoist Q fragments into registers (chunk-invariant) ----
    uint32_t qf[8][4];
    #pragma unroll
    for (int kt = 0; kt < 8; kt++){
        const uint32_t* q0 = smu + Q_F + (wr*16 + fr) * QP + 8*kt + fq;
        qf[kt][0] = q0[0];
        qf[kt][1] = q0[8*QP];
        qf[kt][2] = q0[4];
        qf[kt][3] = q0[8*QP + 4];
    }

    const int erow = tid >> 3, eoct = tid & 7;  // exp-pass coords (row, col-octet)
    float psum = 0.0f;

    // ================= SINGLE S PASS: MMA + exp -> unnormalized tf32 P in smem =================
    for (int c = 0; c < NCH; c++){
        CP_WAIT1;                      // K[c] landed (K[c+1] or V[0] may fly)
        __syncthreads();

        // prefetch dis/mask for this chunk into registers (overlaps the MMAs)
        float4 dv0, dv1; uint4 mv0, mv1;
        {
            const float* dp = disbase + (size_t)erow * NN + c*KC + eoct*4;
            const unsigned int* mp = mbase + (size_t)erow * NN + c*KC + eoct*4;
            dv0 = *(const float4*)dp;        dv1 = *(const float4*)(dp + 32);
            mv0 = *(const uint4*)mp;         mv1 = *(const uint4*)(mp + 32);
        }

        const float* sK = smf + K_F + (c & 1) * KC * KP;
        float sacc[2][4] = {{0.f,0.f,0.f,0.f},{0.f,0.f,0.f,0.f}};
        #pragma unroll
        for (int kt = 0; kt < 8; kt++){
            const int k0 = 8*kt + fq;
            #pragma unroll
            for (int ct = 0; ct < 2; ct++){
                const float* kp = sK + (wc*16 + 8*ct + fr) * KP + k0;
                uint32_t b0 = f2tf32(kp[0]), b1 = f2tf32(kp[4]);
                mma_tf32(sacc[ct], qf[kt], b0, b1);
            }
        }
        // store raw S frags
        #pragma unroll
        for (int ct = 0; ct < 2; ct++){
            int col = c*KC + wc*16 + 8*ct + 2*fq;
            int row = wr*16 + fr;
            *(float2*)(smf + S_F + row*SPP + col)     = make_float2(sacc[ct][0], sacc[ct][1]);
            *(float2*)(smf + S_F + (row+8)*SPP + col) = make_float2(sacc[ct][2], sacc[ct][3]);
        }
        __syncthreads();               // frags visible; K buffer reads done

        // prefetch next K (or first V tiles at the tail)
        if (c < NCH-2){
            cp_tile64(sbase + (K_F + (c & 1)*KC*KP)*4u,
                      kbase + (size_t)(c+2)*KC*CC, tid, KP); CP_COMMIT;
        } else if (c == NCH-2){
            cp_tile64(sbase + V_F*4u, vbase, tid, VP); CP_COMMIT;
        } else {
            cp_tile64(sbase + (V_F + KC*VP)*4u, vbase + (size_t)KC*CC, tid, VP); CP_COMMIT;
        }

        // exp pass (coalesced): P = mask ? 0 : exp((S+dis)/8), unnormalized, stored as tf32 bits
        {
            float* sp = smf + S_F + erow*SPP + c*KC + eoct*4;
            float4 sv0 = *(const float4*)sp;
            float4 sv1 = *(const float4*)(sp + 32);
            float e0 = mv0.x ? 0.f : __expf((sv0.x + dv0.x) * 0.125f);
            float e1 = mv0.y ? 0.f : __expf((sv0.y + dv0.y) * 0.125f);
            float e2 = mv0.z ? 0.f : __expf((sv0.z + dv0.z) * 0.125f);
            float e3 = mv0.w ? 0.f : __expf((sv0.w + dv0.w) * 0.125f);
            float e4 = mv1.x ? 0.f : __expf((sv1.x + dv1.x) * 0.125f);
            float e5 = mv1.y ? 0.f : __expf((sv1.y + dv1.y) * 0.125f);
            float e6 = mv1.z ? 0.f : __expf((sv1.z + dv1.z) * 0.125f);
            float e7 = mv1.w ? 0.f : __expf((sv1.w + dv1.w) * 0.125f);
            psum += (e0+e1) + (e2+e3) + (e4+e5) + (e6+e7);
            *(uint4*)sp         = make_uint4(f2tf32(e0), f2tf32(e1), f2tf32(e2), f2tf32(e3));
            *(uint4*)(sp + 32)  = make_uint4(f2tf32(e4), f2tf32(e5), f2tf32(e6), f2tf32(e7));
        }
    }

    // ---- rowsum reduce (8 lanes per row, unique writer) ----
    {
        float vs = psum;
        vs += __shfl_xor_sync(0xffffffffu, vs, 1);
        vs += __shfl_xor_sync(0xffffffffu, vs, 2);
        vs += __shfl_xor_sync(0xffffffffu, vs, 4);
        if (eoct == 0) smf[RS_F + erow] = vs;
    }
    __syncthreads();
    const float myinv = 1.0f / smf[RS_F + erow];
    const float invA  = 1.0f / smf[RS_F + wr*16 + fr];
    const float invB  = 1.0f / smf[RS_F + wr*16 + fr + 8];

    // ================= PV + normalized P store =================
    float oacc[2][4] = {{0.f,0.f,0.f,0.f},{0.f,0.f,0.f,0.f}};
    for (int p = 0; p < NCH; p++){
        if (p == NCH-1) { CP_WAIT0; } else { CP_WAIT1; }   // V[p] landed
        __syncthreads();
        const float* sV = smf + V_F + (p & 1) * KC * VP;

        #pragma unroll
        for (int kt = 0; kt < 8; kt++){
            const int k0 = p*KC + 8*kt + fq;
            const uint32_t* pp = smu + S_F + (wr*16 + fr) * SPP + k0;   // already tf32 bits
            uint32_t a[4] = { pp[0], pp[8*SPP], pp[4], pp[8*SPP + 4] };
            #pragma unroll
            for (int dt = 0; dt < 2; dt++){
                const int dcol = wc*16 + 8*dt + fr;
                uint32_t b0 = f2tf32(sV[(size_t)(8*kt + fq) * VP + dcol]);
                uint32_t b1 = f2tf32(sV[(size_t)(8*kt + fq + 4) * VP + dcol]);
                mma_tf32(oacc[dt], a, b0, b1);
            }
        }

        // normalized p_attn store (coalesced float4; bits are tf32-valued floats)
        {
            const float* sp = smf + S_F + erow*SPP + p*KC + eoct*4;
            float* dst = pbase + (size_t)erow * NN + p*KC + eoct*4;
            float4 p0 = *(const float4*)sp;
            float4 p1 = *(const float4*)(sp + 32);
            *(float4*)dst        = make_float4(p0.x*myinv, p0.y*myinv, p0.z*myinv, p0.w*myinv);
            *(float4*)(dst + 32) = make_float4(p1.x*myinv, p1.y*myinv, p1.z*myinv, p1.w*myinv);
        }
        __syncthreads();               // V buffer reads done before overwrite
        if (p < NCH-2){
            cp_tile64(sbase + (V_F + (p & 1)*KC*VP)*4u,
                      vbase + (size_t)(p+2)*KC*CC, tid, VP); CP_COMMIT;
        }
    }

    // ---- write O (scaled by row inv) ----
    #pragma unroll
    for (int dt = 0; dt < 2; dt++){
        int gc = h*DD + wc*16 + 8*dt + 2*fq;
        float* o0 = out + ((size_t)b * NN + row0 + wr*16 + fr) * CC + gc;
        *(float2*)o0          = make_float2(oacc[dt][0]*invA, oacc[dt][1]*invA);
        *(float2*)(o0 + 8*CC) = make_float2(oacc[dt][2]*invB, oacc[dt][3]*invB);
    }
}

extern "C" void kernel_launch(void* const* d_in, const int* in_sizes, int n_in,
                              void* d_out, int out_size) {
    const float* q = (const float*)d_in[0];
    const float* k = (const float*)d_in[1];
    const float* v = (const float*)d_in[2];
    const unsigned int* mask = (const unsigned int*)d_in[3];
    const float* dis = (const float*)d_in[4];

    float* out  = (float*)d_out;
    float* pout = out + (size_t)BB * NN * CC;

    cudaFuncSetAttribute(attn_sp2_kernel,
                         cudaFuncAttributeMaxDynamicSharedMemorySize, SMEM_BYTES);

    dim3 grid((NN / QT) * HEADS, BB, 1);
    attn_sp2_kernel<<<grid, 256, SMEM_BYTES>>>(q, k, v, mask, dis, out, pout);
}

// round 12
// speedup vs baseline: 2.4313x; 1.2930x over previous
#include <cuda_runtime.h>
#include <math.h>
#include <stdint.h>

#define HEADS 4
#define BB 8
#define NN 1024
#define CC 256
#define DD 64
#define QT 32            // query rows per CTA
#define KC 32            // keys per chunk
#define NCH 32           // chunks

#define KP 68            // K pitch: (4fr+fq)%32 distinct -> conflict-free B frags
#define VP 72            // V pitch: (8fq+fr)%32 distinct -> conflict-free B frags
#define DP 36            // dis/mask chunk pitch
#define OP 68            // O scratch pitch

// float-index smem offsets
#define Q_F   0                     // 32*68          = 2176
#define K_F   2176                  // 2 * 32*68      = 4352
#define V_F   6528                  // 2 * 32*72      = 4608
#define D_F   11136                 // 2 * 32*36      = 2304
#define M_F   13440                 // 2 * 32*36      = 2304
#define OS_F  15744                 // 32*68          = 2176
#define RS_F  17920                 // 32
#define SMEM_FLOATS 17952
#define SMEM_BYTES (SMEM_FLOATS*4)  // 71808

#define KSTR (32*KP)
#define VSTR (32*VP)
#define DSTR (32*DP)

#define CP_COMMIT   asm volatile("cp.async.commit_group;" ::: "memory")
#define CP_WAIT0    asm volatile("cp.async.wait_group 0;" ::: "memory")

static __device__ __forceinline__ uint32_t s2u(const void* p){
    uint32_t a;
    asm("{ .reg .u64 t; cvta.to.shared.u64 t, %1; cvt.u32.u64 %0, t; }" : "=r"(a) : "l"(p));
    return a;
}
static __device__ __forceinline__ uint32_t f2tf32(float f){
    uint32_t u; asm("cvt.rna.tf32.f32 %0, %1;" : "=r"(u) : "f"(f)); return u;
}
static __device__ __forceinline__ void mma_tf32(float* c, const uint32_t* a,
                                                uint32_t b0, uint32_t b1){
    asm volatile("mma.sync.aligned.m16n8k8.row.col.f32.tf32.tf32.f32 "
        "{%0,%1,%2,%3}, {%4,%5,%6,%7}, {%8,%9}, {%0,%1,%2,%3};"
        : "+f"(c[0]), "+f"(c[1]), "+f"(c[2]), "+f"(c[3])
        : "r"(a[0]), "r"(a[1]), "r"(a[2]), "r"(a[3]), "r"(b0), "r"(b1));
}
#define CPA16(dst, src) \
    asm volatile("cp.async.ca.shared.global [%0], [%1], 16;" :: "r"(dst), "l"(src) : "memory")

__global__ __launch_bounds__(256, 2)
void attn_fuse_kernel(const float* __restrict__ q,
                      const float* __restrict__ k,
                      const float* __restrict__ v,
                      const unsigned int* __restrict__ mask,
                      const float* __restrict__ dis,
                      float* __restrict__ out,
                      float* __restrict__ pout)
{
    extern __shared__ float smf[];
    uint32_t* smu = (uint32_t*)smf;
    const uint32_t sbase = s2u(smf);

    const int tid  = threadIdx.x;
    const int wid  = tid >> 5;
    const int lane = tid & 31;
    const int fr = lane >> 2, fq = lane & 3;
    const int wr = wid >> 2, wc = wid & 3;     // 2 row-groups x 4 col-groups
    const int h    = blockIdx.x & 3;           // heads fastest -> dis/mask L2 reuse
    const int tile = blockIdx.x >> 2;
    const int b    = blockIdx.y;
    const int row0 = tile * QT;

    const float* qbase = q + ((size_t)b * NN + row0) * CC + h * DD;
    const float* kbase = k + ((size_t)b * NN) * CC + h * DD;
    const float* vbase = v + ((size_t)b * NN) * CC + h * DD;
    const float* disbase = dis + ((size_t)b * NN + row0) * NN;
    const unsigned int* mbase = mask + ((size_t)b * NN + row0) * NN;
    float* pbase = pout + (((size_t)h * BB + b) * NN + row0) * NN;

    // staging coords
    const int sr = tid >> 3;                   // 0..31
    const int sc = (tid & 7);                  // octet

    // ---- issue chunk 0 (K,V,dis,mask) ----
    {
        const float* ks = kbase + (size_t)sr * CC + sc*8;
        const float* vs = vbase + (size_t)sr * CC + sc*8;
        uint32_t kd = sbase + (K_F + sr*KP + sc*8)*4u;
        uint32_t vd = sbase + (V_F + sr*VP + sc*8)*4u;
        CPA16(kd, ks); CPA16(kd+16u, ks+4);
        CPA16(vd, vs); CPA16(vd+16u, vs+4);
        CPA16(sbase + (D_F + sr*DP + sc*4)*4u, disbase + (size_t)sr*NN + sc*4);
        CPA16(sbase + (M_F + sr*DP + sc*4)*4u, mbase   + (size_t)sr*NN + sc*4);
    }
    CP_COMMIT;

    // ---- stage Q (fp32 -> tf32), zero scratch ----
    {
        const float* src = qbase + (size_t)sr * CC + sc*8;
        float4 v0 = *(const float4*)src;
        float4 v1 = *(const float4*)(src + 4);
        uint32_t* d = smu + Q_F + sr * KP + sc*8;
        *(uint4*)d       = make_uint4(f2tf32(v0.x), f2tf32(v0.y), f2tf32(v0.z), f2tf32(v0.w));
        *(uint4*)(d + 4) = make_uint4(f2tf32(v1.x), f2tf32(v1.y), f2tf32(v1.z), f2tf32(v1.w));
    }
    for (int i = tid; i < 2176 + 32; i += 256) smf[OS_F + i] = 0.0f;
    __syncthreads();

    // ---- hoist Q fragments ----
    uint32_t qf[8][4];
    #pragma unroll
    for (int kt = 0; kt < 8; kt++){
        const uint32_t* q0 = smu + Q_F + (wr*16 + fr) * KP + 8*kt + fq;
        qf[kt][0] = q0[0];
        qf[kt][1] = q0[8*KP];
        qf[kt][2] = q0[4];
        qf[kt][3] = q0[8*KP + 4];
    }

    const int r1 = wr*16 + fr;         // CTA-local row
    const int ccl = wc*8 + 2*fq;       // chunk-local col
    const int srcA = (lane & 28) | (fq >> 1);
    const int srcB = srcA + 2;
    const bool odd = (fq & 1);

    float psum0 = 0.f, psum1 = 0.f;
    float oacc[8][4];
    #pragma unroll
    for (int dt = 0; dt < 8; dt++)
        #pragma unroll
        for (int i = 0; i < 4; i++) oacc[dt][i] = 0.f;

    // ================= fused mainloop =================
    for (int c = 0; c < NCH; c++){
        CP_WAIT0;
        __syncthreads();               // publish chunk c; retire reads of chunk c-1

        if (c + 1 < NCH){              // prefetch chunk c+1 into other buffers
            int bb1 = (c + 1) & 1;
            const float* ks = kbase + (size_t)((c+1)*KC + sr) * CC + sc*8;
            const float* vs = vbase + (size_t)((c+1)*KC + sr) * CC + sc*8;
            uint32_t kd = sbase + (K_F + bb1*KSTR + sr*KP + sc*8)*4u;
            uint32_t vd = sbase + (V_F + bb1*VSTR + sr*VP + sc*8)*4u;
            CPA16(kd, ks); CPA16(kd+16u, ks+4);
            CPA16(vd, vs); CPA16(vd+16u, vs+4);
            CPA16(sbase + (D_F + bb1*DSTR + sr*DP + sc*4)*4u,
                  disbase + (size_t)sr*NN + (c+1)*KC + sc*4);
            CPA16(sbase + (M_F + bb1*DSTR + sr*DP + sc*4)*4u,
                  mbase   + (size_t)sr*NN + (c+1)*KC + sc*4);
            CP_COMMIT;
        }

        const int bb = c & 1;
        // ---- S = Q K^T (warp tile 16x8) ----
        const float* sK = smf + K_F + bb*KSTR;
        float sacc[4] = {0.f, 0.f, 0.f, 0.f};
        #pragma unroll
        for (int kt = 0; kt < 8; kt++){
            const float* kp = sK + (wc*8 + fr) * KP + 8*kt + fq;
            uint32_t b0 = f2tf32(kp[0]), b1 = f2tf32(kp[4]);
            mma_tf32(sacc, qf[kt], b0, b1);
        }

        // ---- fragment exp with smem dis/mask ----
        const float* sD = smf + D_F + bb*DSTR;
        const uint32_t* sM = smu + M_F + bb*DSTR;
        float2 d0 = *(const float2*)(sD + r1*DP + ccl);
        float2 d1 = *(const float2*)(sD + (r1+8)*DP + ccl);
        uint2  m0 = *(const uint2*) (sM + r1*DP + ccl);
        uint2  m1 = *(const uint2*) (sM + (r1+8)*DP + ccl);
        float e0 = m0.x ? 0.f : __expf((sacc[0] + d0.x) * 0.125f);
        float e1 = m0.y ? 0.f : __expf((sacc[1] + d0.y) * 0.125f);
        float e2 = m1.x ? 0.f : __expf((sacc[2] + d1.x) * 0.125f);
        float e3 = m1.y ? 0.f : __expf((sacc[3] + d1.y) * 0.125f);
        psum0 += e0 + e1;
        psum1 += e2 + e3;
        uint32_t u0 = f2tf32(e0), u1 = f2tf32(e1), u2 = f2tf32(e2), u3 = f2tf32(e3);

        // ---- store unnormalized P to gmem (32B sector-aligned per 4-lane group) ----
        {
            float* pr = pbase + (size_t)r1 * NN + c*KC + ccl;
            *(uint2*)pr           = make_uint2(u0, u1);
            *(uint2*)(pr + 8*NN)  = make_uint2(u2, u3);
        }

        // ---- A-frags for PV via warp shuffles (C-layout -> A-layout) ----
        uint32_t a[4];
        {
            uint32_t s0a = __shfl_sync(0xffffffffu, u0, srcA);
            uint32_t s1a = __shfl_sync(0xffffffffu, u1, srcA);
            uint32_t s2a = __shfl_sync(0xffffffffu, u2, srcA);
            uint32_t s3a = __shfl_sync(0xffffffffu, u3, srcA);
            uint32_t s0b = __shfl_sync(0xffffffffu, u0, srcB);
            uint32_t s1b = __shfl_sync(0xffffffffu, u1, srcB);
            uint32_t s2b = __shfl_sync(0xffffffffu, u2, srcB);
            uint32_t s3b = __shfl_sync(0xffffffffu, u3, srcB);
            a[0] = odd ? s1a : s0a;    // (fr,   k=fq)
            a[1] = odd ? s3a : s2a;    // (fr+8, k=fq)
            a[2] = odd ? s1b : s0b;    // (fr,   k=fq+4)
            a[3] = odd ? s3b : s2b;    // (fr+8, k=fq+4)
        }

        // ---- PV: O_partial[16 x 64] += P(16x8) * V(8x64) ----
        const float* sV = smf + V_F + bb*VSTR;
        #pragma unroll
        for (int dt = 0; dt < 8; dt++){
            uint32_t b0 = f2tf32(sV[(wc*8 + fq)     * VP + 8*dt + fr]);
            uint32_t b1 = f2tf32(sV[(wc*8 + fq + 4) * VP + 8*dt + fr]);
            mma_tf32(oacc[dt], a, b0, b1);
        }
    }

    // ---- rowsum reduce ----
    {
        float v0 = psum0, v1 = psum1;
        v0 += __shfl_xor_sync(0xffffffffu, v0, 1);
        v0 += __shfl_xor_sync(0xffffffffu, v0, 2);
        v1 += __shfl_xor_sync(0xffffffffu, v1, 1);
        v1 += __shfl_xor_sync(0xffffffffu, v1, 2);
        if (fq == 0){
            atomicAdd(smf + RS_F + r1, v0);
            atomicAdd(smf + RS_F + r1 + 8, v1);
        }
    }
    // ---- O cross-warp (wc) reduce into scratch ----
    #pragma unroll
    for (int dt = 0; dt < 8; dt++){
        atomicAdd(smf + OS_F + r1*OP     + 8*dt + 2*fq,     oacc[dt][0]);
        atomicAdd(smf + OS_F + r1*OP     + 8*dt + 2*fq + 1, oacc[dt][1]);
        atomicAdd(smf + OS_F + (r1+8)*OP + 8*dt + 2*fq,     oacc[dt][2]);
        atomicAdd(smf + OS_F + (r1+8)*OP + 8*dt + 2*fq + 1, oacc[dt][3]);
    }
    __syncthreads();

    // ---- write O (scaled) ----
    {
        const float inv = 1.0f / smf[RS_F + sr];
        const float* src = smf + OS_F + sr*OP + sc*8;
        float* dst = out + ((size_t)b * NN + row0 + sr) * CC + h * DD + sc*8;
        float4 a0 = *(const float4*)src;
        float4 a1 = *(const float4*)(src + 4);
        *(float4*)dst       = make_float4(a0.x*inv, a0.y*inv, a0.z*inv, a0.w*inv);
        *(float4*)(dst + 4) = make_float4(a1.x*inv, a1.y*inv, a1.z*inv, a1.w*inv);
    }

    // ---- renormalize own p_attn strip in place (L2-hot) ----
    {
        const float inv = 1.0f / smf[RS_F + sr];
        float* prow = pbase + (size_t)sr * NN;
        #pragma unroll 4
        for (int j = 0; j < 32; j++){
            float* p4 = prow + sc*4 + 32*j;
            float4 pv = *(const float4*)p4;
            *(float4*)p4 = make_float4(pv.x*inv, pv.y*inv, pv.z*inv, pv.w*inv);
        }
    }
}

extern "C" void kernel_launch(void* const* d_in, const int* in_sizes, int n_in,
                              void* d_out, int out_size) {
    const float* q = (const float*)d_in[0];
    const float* k = (const float*)d_in[1];
    const float* v = (const float*)d_in[2];
    const unsigned int* mask = (const unsigned int*)d_in[3];
    const float* dis = (const float*)d_in[4];

    float* out  = (float*)d_out;
    float* pout = out + (size_t)BB * NN * CC;

    cudaFuncSetAttribute(attn_fuse_kernel,
                         cudaFuncAttributeMaxDynamicSharedMemorySize, SMEM_BYTES);

    dim3 grid((NN / QT) * HEADS, BB, 1);
    attn_fuse_kernel<<<grid, 256, SMEM_BYTES>>>(q, k, v, mask, dis, out, pout);
}